// round 11
// baseline (speedup 1.0000x reference)
#include <cuda_runtime.h>
#include <cuda_fp16.h>
#include <math.h>

#define N_NODES 50000
#define N_EDGES 1600000
#define BATCH   2
#define C       64
#define CAP     192
#define NBLK    ((N_NODES + 255) / 256)

// ---- scratch ----
__device__ int    g_cnt[N_NODES];
__device__ int    g_cursor[N_NODES];
__device__ float4 g_ni[N_NODES];      // {flux_b0, flux_b1, dis, 0}
// interleaved per (batch,node) row: [xc: 64 halfs][xd: 64 halfs] = 256 B
__device__ __align__(16) __half g_xi[(size_t)BATCH * N_NODES * 2 * C];
// fixed-capacity buckets: slot = tgt*CAP + k ; {src(int bits), norm, cC_b0, cC_b1}
__device__ float4 g_em[(size_t)N_NODES * CAP];
__device__ int    g_is64;

// ---- packed f32x2 helpers ----
__device__ __forceinline__ unsigned long long pk2(float x, float y) {
    unsigned long long r;
    asm("mov.b64 %0, {%1,%2};" : "=l"(r) : "f"(x), "f"(y));
    return r;
}
__device__ __forceinline__ void upk2(unsigned long long v, float& x, float& y) {
    asm("mov.b64 {%0,%1}, %2;" : "=f"(x), "=f"(y) : "l"(v));
}
__device__ __forceinline__ void fma2(unsigned long long& c,
                                     unsigned long long a,
                                     unsigned long long b) {
    asm("fma.rn.f32x2 %0, %1, %2, %0;" : "+l"(c) : "l"(a), "l"(b));
}
__device__ __forceinline__ void add2(unsigned long long& c, unsigned long long a) {
    asm("add.rn.f32x2 %0, %0, %1;" : "+l"(c) : "l"(a));
}
__device__ __forceinline__ float tanh_fast(float x) {
    asm("tanh.approx.f32 %0, %0;" : "+f"(x));
    return x;
}

// ---------------------------------------------------------------------------
__global__ void detect_zero_kernel(const unsigned int* __restrict__ w) {
    int i = blockIdx.x * blockDim.x + threadIdx.x;
    if (i < N_NODES) { g_cnt[i] = 0; g_cursor[i] = 0; }
    if (blockIdx.x == 0) {
        __shared__ unsigned int acc;
        if (threadIdx.x == 0) acc = 0u;
        __syncthreads();
        unsigned int v = 0u;
        for (int j = threadIdx.x; j < 4096; j += blockDim.x)
            v |= w[(size_t)2 * j * 97 + 1];
        atomicOr(&acc, v);
        __syncthreads();
        if (threadIdx.x == 0) g_is64 = (acc == 0u) ? 1 : 0;
    }
}

__device__ __forceinline__ int load_idx(const int* __restrict__ ei, size_t e) {
    return g_is64 ? ei[2 * e] : ei[e];
}

// 4 edges per thread
__global__ void hist_kernel(const int* __restrict__ ei) {
    int e4 = (blockIdx.x * blockDim.x + threadIdx.x) * 4;
    if (e4 >= N_EDGES) return;
    int t0, t1, t2, t3;
    if (g_is64) {
        const int4 v0 = *(const int4*)(ei + 2 * ((size_t)N_EDGES + e4));
        const int4 v1 = *(const int4*)(ei + 2 * ((size_t)N_EDGES + e4) + 4);
        t0 = v0.x; t1 = v0.z; t2 = v1.x; t3 = v1.z;
    } else {
        const int4 v = *(const int4*)(ei + (size_t)N_EDGES + e4);
        t0 = v.x; t1 = v.y; t2 = v.z; t3 = v.w;
    }
    atomicAdd(&g_cnt[t0], 1);
    atomicAdd(&g_cnt[t1], 1);
    atomicAdd(&g_cnt[t2], 1);
    atomicAdd(&g_cnt[t3], 1);
}

// node info: dis from degree + fluxes
__global__ void ni_kernel(const float* __restrict__ fluxes) {
    int i = blockIdx.x * blockDim.x + threadIdx.x;
    if (i < N_NODES) {
        const float dis = rsqrtf((float)(g_cnt[i] + 1));
        g_ni[i] = make_float4(fluxes[i], fluxes[N_NODES + i], dis, 0.0f);
    }
}

// ---------------------------------------------------------------------------
// fill fixed-capacity buckets: single 16 B meta per edge serving both batches.
// cD_b = norm - cC_b (exact).
// ---------------------------------------------------------------------------
__global__ void __launch_bounds__(256)
fill_kernel(const int* __restrict__ ei,
            const float* __restrict__ fdo) {
    int e = blockIdx.x * blockDim.x + threadIdx.x;
    if (e >= N_EDGES) return;
    int s = load_idx(ei, e);
    int t = load_idx(ei, (size_t)N_EDGES + e);

    int pos = t * CAP + atomicAdd(&g_cursor[t], 1);

    const float4 nis = __ldg(&g_ni[s]);
    const float4 nit = __ldg(&g_ni[t]);

    const float f0   = fdo[e];
    const float norm = nis.z * nit.z;

    const float k0 = 0.5f * (1.0f + tanh_fast(nis.x * nit.x));
    const float k1 = 0.5f * (1.0f + tanh_fast(nis.y * nit.y));
    const float fb0 = k0 * f0 + (1.0f - k0) * (1.0f - f0);
    const float fb1 = k1 * f0 + (1.0f - k1) * (1.0f - f0);

    g_em[pos] = make_float4(__int_as_float(s), norm,
                            norm * (1.0f - fb0), norm * (1.0f - fb1));
}

// ---------------------------------------------------------------------------
// Dual GEMM -> interleaved fp16 rows [xc(64)|xd(64)]. FFMA2-packed.
// ---------------------------------------------------------------------------
__global__ void __launch_bounds__(256)
gemm_kernel(const float* __restrict__ x,
            const float* __restrict__ Wc,
            const float* __restrict__ Wd) {
    const int o  = threadIdx.x >> 2;
    const int kg = threadIdx.x & 3;

    unsigned long long wp[16];
#pragma unroll
    for (int i = 0; i < 16; i++)
        wp[i] = pk2(Wc[o * C + kg * 16 + i], Wd[o * C + kg * 16 + i]);

    __shared__ __align__(16) float xs[4][C];
    const int M = BATCH * N_NODES;
    const int lr = threadIdx.x >> 6;
    const int lc = threadIdx.x & 63;

    for (int m0 = blockIdx.x * 4; m0 < M; m0 += gridDim.x * 4) {
        __syncthreads();
        xs[lr][lc] = x[(size_t)(m0 + lr) * C + lc];
        __syncthreads();

#pragma unroll
        for (int r2 = 0; r2 < 4; r2++) {
            const float4* xp = (const float4*)&xs[r2][kg * 16];
            unsigned long long acc = 0ull;
#pragma unroll
            for (int j = 0; j < 4; j++) {
                float4 xv = xp[j];
                fma2(acc, pk2(xv.x, xv.x), wp[4 * j + 0]);
                fma2(acc, pk2(xv.y, xv.y), wp[4 * j + 1]);
                fma2(acc, pk2(xv.z, xv.z), wp[4 * j + 2]);
                fma2(acc, pk2(xv.w, xv.w), wp[4 * j + 3]);
            }
            float sc, sd;
            upk2(acc, sc, sd);
            sc += __shfl_xor_sync(0xffffffffu, sc, 1);
            sc += __shfl_xor_sync(0xffffffffu, sc, 2);
            sd += __shfl_xor_sync(0xffffffffu, sd, 1);
            sd += __shfl_xor_sync(0xffffffffu, sd, 2);
            float sc2 = __shfl_xor_sync(0xffffffffu, sc, 4);
            float sd2 = __shfl_xor_sync(0xffffffffu, sd, 4);

            if (kg == 0 && (o & 1) == 0) {
                __half* row = g_xi + (size_t)(m0 + r2) * (2 * C);
                *(__half2*)(row + o)     = __floats2half2_rn(sc, sc2);
                *(__half2*)(row + C + o) = __floats2half2_rn(sd, sd2);
            }
        }
    }
}

// ---------------------------------------------------------------------------
// Gather: 128-thread blocks, >=6 blocks/SM forced (occupancy is the measured
// binding constraint). One warp per (node,batch), batch-major. Four 8-lane
// groups; 4 edges per trip, all 8 row LDG.128s issued up front. fp16 core,
// flush to f32x2 accumulators every 2 edges. Branch-free tail via clamp.
// ---------------------------------------------------------------------------
__global__ void __launch_bounds__(128, 6)
gather_kernel(const float* __restrict__ bias, float* __restrict__ out) {
    const int w = (int)((blockIdx.x * blockDim.x + threadIdx.x) >> 5);
    if (w >= BATCH * N_NODES) return;
    const int b    = (w < N_NODES) ? 0 : 1;
    const int n    = (w < N_NODES) ? w : (w - N_NODES);
    const int lane = threadIdx.x & 31;
    const int g    = lane >> 3;        // edge group 0..3
    const int l8   = lane & 7;         // 8 channels: l8*8 .. +8

    const int beg = n * CAP;
    const int end = beg + g_cnt[n];

    const __half*  __restrict__ xib = g_xi + (size_t)b * N_NODES * (2 * C);

    unsigned long long a0 = 0ull, a1 = 0ull, a2 = 0ull, a3 = 0ull;

    if (g == 0) {   // self-loop + bias init
        const float4 ni = g_ni[n];
        const float nrm = ni.z * ni.z;
        const float4 b0 = *(const float4*)(bias + l8 * 8);
        const float4 b1 = *(const float4*)(bias + l8 * 8 + 4);
        const uint4  xh = *(const uint4*)(xib + (size_t)n * (2 * C) + l8 * 8);
        const float2 x0 = __half22float2(*(const __half2*)&xh.x);
        const float2 x1 = __half22float2(*(const __half2*)&xh.y);
        const float2 x2 = __half22float2(*(const __half2*)&xh.z);
        const float2 x3 = __half22float2(*(const __half2*)&xh.w);
        a0 = pk2(fmaf(nrm, x0.x, b0.x), fmaf(nrm, x0.y, b0.y));
        a1 = pk2(fmaf(nrm, x1.x, b0.z), fmaf(nrm, x1.y, b0.w));
        a2 = pk2(fmaf(nrm, x2.x, b1.x), fmaf(nrm, x2.y, b1.y));
        a3 = pk2(fmaf(nrm, x3.x, b1.z), fmaf(nrm, x3.y, b1.w));
    }

    int i = beg + g;                   // this group's slots: i, i+4, i+8, i+12
    if (i < end) {
        const int last = end - 1;
        // per-edge state: (src, cC, cD) with cD = norm - cC
        float3 m[4];
#pragma unroll
        for (int k = 0; k < 4; k++) {
            const int  j = i + 4 * k;
            const bool v = (j < end);
            const float4 t = __ldg(&g_em[v ? j : last]);
            const float cC = v ? (b ? t.w : t.z) : 0.0f;
            const float nm = v ? t.y : 0.0f;
            m[k] = make_float3(t.x, cC, nm - cC);
        }

        for (;;) {
            // 1) issue all 8 row loads (max lines in flight)
            uint4 A[4], D[4];
#pragma unroll
            for (int k = 0; k < 4; k++) {
                const __half* row = xib +
                    (size_t)__float_as_int(m[k].x) * (2 * C) + l8 * 8;
                A[k] = __ldg((const uint4*)(row));
                D[k] = __ldg((const uint4*)(row + C));
            }

            // 2) prefetch next 4 metas (clamped; harmless when exiting)
            i += 16;
            const bool more = (i < end);
            float3 mn[4];
#pragma unroll
            for (int k = 0; k < 4; k++) {
                const int  j = i + 4 * k;
                const bool v = (j < end);
                const float4 t = __ldg(&g_em[v ? j : last]);
                const float cC = v ? (b ? t.w : t.z) : 0.0f;
                const float nm = v ? t.y : 0.0f;
                mn[k] = make_float3(t.x, cC, nm - cC);
            }

            // 3) consume: fp16 core, flush every 2 edges
#pragma unroll
            for (int p = 0; p < 2; p++) {
                const int k0 = 2 * p, k1 = 2 * p + 1;
                const __half2 cc0 = __float2half2_rn(m[k0].y);
                const __half2 cd0 = __float2half2_rn(m[k0].z);
                const __half2 cc1 = __float2half2_rn(m[k1].y);
                const __half2 cd1 = __float2half2_rn(m[k1].z);
                const __half2* A0 = (const __half2*)&A[k0];
                const __half2* D0 = (const __half2*)&D[k0];
                const __half2* A1 = (const __half2*)&A[k1];
                const __half2* D1 = (const __half2*)&D[k1];

                __half2 h0 = __hmul2(A0[0], cc0);
                __half2 h1 = __hmul2(A0[1], cc0);
                __half2 h2 = __hmul2(A0[2], cc0);
                __half2 h3 = __hmul2(A0[3], cc0);
                h0 = __hfma2(D0[0], cd0, h0);
                h1 = __hfma2(D0[1], cd0, h1);
                h2 = __hfma2(D0[2], cd0, h2);
                h3 = __hfma2(D0[3], cd0, h3);
                h0 = __hfma2(A1[0], cc1, h0);
                h1 = __hfma2(A1[1], cc1, h1);
                h2 = __hfma2(A1[2], cc1, h2);
                h3 = __hfma2(A1[3], cc1, h3);
                h0 = __hfma2(D1[0], cd1, h0);
                h1 = __hfma2(D1[1], cd1, h1);
                h2 = __hfma2(D1[2], cd1, h2);
                h3 = __hfma2(D1[3], cd1, h3);

                float2 f;
                f = __half22float2(h0); add2(a0, pk2(f.x, f.y));
                f = __half22float2(h1); add2(a1, pk2(f.x, f.y));
                f = __half22float2(h2); add2(a2, pk2(f.x, f.y));
                f = __half22float2(h3); add2(a3, pk2(f.x, f.y));
            }

            if (!more) break;
#pragma unroll
            for (int k = 0; k < 4; k++) m[k] = mn[k];
        }
    }

    // reduce the 4 groups
    float f0, f1, f2, f3, f4, f5, f6, f7;
    upk2(a0, f0, f1); upk2(a1, f2, f3); upk2(a2, f4, f5); upk2(a3, f6, f7);
#pragma unroll
    for (int d = 8; d <= 16; d <<= 1) {
        f0 += __shfl_xor_sync(0xffffffffu, f0, d);
        f1 += __shfl_xor_sync(0xffffffffu, f1, d);
        f2 += __shfl_xor_sync(0xffffffffu, f2, d);
        f3 += __shfl_xor_sync(0xffffffffu, f3, d);
        f4 += __shfl_xor_sync(0xffffffffu, f4, d);
        f5 += __shfl_xor_sync(0xffffffffu, f5, d);
        f6 += __shfl_xor_sync(0xffffffffu, f6, d);
        f7 += __shfl_xor_sync(0xffffffffu, f7, d);
    }

    if (g == 0) {
        float* orow = out + ((size_t)b * N_NODES + n) * C + l8 * 8;
        *(float4*)(orow)     = make_float4(f0, f1, f2, f3);
        *(float4*)(orow + 4) = make_float4(f4, f5, f6, f7);
    }
}

// ---------------------------------------------------------------------------
extern "C" void kernel_launch(void* const* d_in, const int* in_sizes, int n_in,
                              void* d_out, int out_size) {
    const float* x    = (const float*)d_in[0];
    const int*   ei   = (const int*)d_in[1];
    const float* fdo  = (const float*)d_in[2];
    const float* flux = (const float*)d_in[3];
    const float* Wc   = (const float*)d_in[4];
    const float* Wd   = (const float*)d_in[5];
    const float* bias = (const float*)d_in[6];
    float* out = (float*)d_out;

    static cudaStream_t s2 = nullptr;
    static cudaEvent_t evFork = nullptr, evJoin = nullptr;
    if (!s2) {
        cudaStreamCreateWithFlags(&s2, cudaStreamNonBlocking);
        cudaEventCreateWithFlags(&evFork, cudaEventDisableTiming);
        cudaEventCreateWithFlags(&evJoin, cudaEventDisableTiming);
    }

    cudaEventRecord(evFork, 0);
    cudaStreamWaitEvent(s2, evFork, 0);
    gemm_kernel<<<2960, 256, 0, s2>>>(x, Wc, Wd);
    cudaEventRecord(evJoin, s2);

    detect_zero_kernel<<<NBLK, 256>>>((const unsigned int*)ei);
    hist_kernel<<<(N_EDGES / 4 + 255) / 256, 256>>>(ei);
    ni_kernel<<<NBLK, 256>>>(flux);
    fill_kernel<<<(N_EDGES + 255) / 256, 256>>>(ei, fdo);

    cudaStreamWaitEvent(0, evJoin, 0);
    gather_kernel<<<(BATCH * N_NODES * 32 + 127) / 128, 128>>>(bias, out);
}

// round 12
// speedup vs baseline: 1.0376x; 1.0376x over previous
#include <cuda_runtime.h>
#include <cuda_fp16.h>
#include <math.h>

#define N_NODES 50000
#define N_EDGES 1600000
#define BATCH   2
#define C       64
#define CAP     192
#define NBLK    ((N_NODES + 255) / 256)

// ---- scratch ----
__device__ int    g_cnt[N_NODES];
__device__ int    g_cursor[N_NODES];
__device__ float4 g_ni[N_NODES];      // {flux_b0, flux_b1, dis, 0}
// interleaved per (batch,node) row: [xc: 64 halfs][xd: 64 halfs] = 256 B
__device__ __align__(16) __half g_xi[(size_t)BATCH * N_NODES * 2 * C];
// fixed-capacity buckets: slot = tgt*CAP + k ; {src(int bits), norm, cC_b0, cC_b1}
__device__ float4 g_em[(size_t)N_NODES * CAP];
__device__ int    g_is64;

// ---- packed f32x2 helpers ----
__device__ __forceinline__ unsigned long long pk2(float x, float y) {
    unsigned long long r;
    asm("mov.b64 %0, {%1,%2};" : "=l"(r) : "f"(x), "f"(y));
    return r;
}
__device__ __forceinline__ void upk2(unsigned long long v, float& x, float& y) {
    asm("mov.b64 {%0,%1}, %2;" : "=f"(x), "=f"(y) : "l"(v));
}
__device__ __forceinline__ void fma2(unsigned long long& c,
                                     unsigned long long a,
                                     unsigned long long b) {
    asm("fma.rn.f32x2 %0, %1, %2, %0;" : "+l"(c) : "l"(a), "l"(b));
}
__device__ __forceinline__ void add2(unsigned long long& c, unsigned long long a) {
    asm("add.rn.f32x2 %0, %0, %1;" : "+l"(c) : "l"(a));
}
__device__ __forceinline__ float tanh_fast(float x) {
    asm("tanh.approx.f32 %0, %0;" : "+f"(x));
    return x;
}

// ---------------------------------------------------------------------------
__global__ void detect_zero_kernel(const unsigned int* __restrict__ w) {
    int i = blockIdx.x * blockDim.x + threadIdx.x;
    if (i < N_NODES) { g_cnt[i] = 0; g_cursor[i] = 0; }
    if (blockIdx.x == 0) {
        __shared__ unsigned int acc;
        if (threadIdx.x == 0) acc = 0u;
        __syncthreads();
        unsigned int v = 0u;
        for (int j = threadIdx.x; j < 4096; j += blockDim.x)
            v |= w[(size_t)2 * j * 97 + 1];
        atomicOr(&acc, v);
        __syncthreads();
        if (threadIdx.x == 0) g_is64 = (acc == 0u) ? 1 : 0;
    }
}

__device__ __forceinline__ int load_idx(const int* __restrict__ ei, size_t e) {
    return g_is64 ? ei[2 * e] : ei[e];
}

// 4 edges per thread
__global__ void hist_kernel(const int* __restrict__ ei) {
    int e4 = (blockIdx.x * blockDim.x + threadIdx.x) * 4;
    if (e4 >= N_EDGES) return;
    int t0, t1, t2, t3;
    if (g_is64) {
        const int4 v0 = *(const int4*)(ei + 2 * ((size_t)N_EDGES + e4));
        const int4 v1 = *(const int4*)(ei + 2 * ((size_t)N_EDGES + e4) + 4);
        t0 = v0.x; t1 = v0.z; t2 = v1.x; t3 = v1.z;
    } else {
        const int4 v = *(const int4*)(ei + (size_t)N_EDGES + e4);
        t0 = v.x; t1 = v.y; t2 = v.z; t3 = v.w;
    }
    atomicAdd(&g_cnt[t0], 1);
    atomicAdd(&g_cnt[t1], 1);
    atomicAdd(&g_cnt[t2], 1);
    atomicAdd(&g_cnt[t3], 1);
}

// node info: dis from degree + fluxes
__global__ void ni_kernel(const float* __restrict__ fluxes) {
    int i = blockIdx.x * blockDim.x + threadIdx.x;
    if (i < N_NODES) {
        const float dis = rsqrtf((float)(g_cnt[i] + 1));
        g_ni[i] = make_float4(fluxes[i], fluxes[N_NODES + i], dis, 0.0f);
    }
}

// ---------------------------------------------------------------------------
// fill fixed-capacity buckets: single 16 B meta per edge serving both batches.
// cD_b = norm - cC_b (exact).
// ---------------------------------------------------------------------------
__global__ void __launch_bounds__(256)
fill_kernel(const int* __restrict__ ei,
            const float* __restrict__ fdo) {
    int e = blockIdx.x * blockDim.x + threadIdx.x;
    if (e >= N_EDGES) return;
    int s = load_idx(ei, e);
    int t = load_idx(ei, (size_t)N_EDGES + e);

    int pos = t * CAP + atomicAdd(&g_cursor[t], 1);

    const float4 nis = __ldg(&g_ni[s]);
    const float4 nit = __ldg(&g_ni[t]);

    const float f0   = fdo[e];
    const float norm = nis.z * nit.z;

    const float k0 = 0.5f * (1.0f + tanh_fast(nis.x * nit.x));
    const float k1 = 0.5f * (1.0f + tanh_fast(nis.y * nit.y));
    const float fb0 = k0 * f0 + (1.0f - k0) * (1.0f - f0);
    const float fb1 = k1 * f0 + (1.0f - k1) * (1.0f - f0);

    g_em[pos] = make_float4(__int_as_float(s), norm,
                            norm * (1.0f - fb0), norm * (1.0f - fb1));
}

// ---------------------------------------------------------------------------
// Dual GEMM -> interleaved fp16 rows [xc(64)|xd(64)]. FFMA2-packed.
// ---------------------------------------------------------------------------
__global__ void __launch_bounds__(256)
gemm_kernel(const float* __restrict__ x,
            const float* __restrict__ Wc,
            const float* __restrict__ Wd) {
    const int o  = threadIdx.x >> 2;
    const int kg = threadIdx.x & 3;

    unsigned long long wp[16];
#pragma unroll
    for (int i = 0; i < 16; i++)
        wp[i] = pk2(Wc[o * C + kg * 16 + i], Wd[o * C + kg * 16 + i]);

    __shared__ __align__(16) float xs[4][C];
    const int M = BATCH * N_NODES;
    const int lr = threadIdx.x >> 6;
    const int lc = threadIdx.x & 63;

    for (int m0 = blockIdx.x * 4; m0 < M; m0 += gridDim.x * 4) {
        __syncthreads();
        xs[lr][lc] = x[(size_t)(m0 + lr) * C + lc];
        __syncthreads();

#pragma unroll
        for (int r2 = 0; r2 < 4; r2++) {
            const float4* xp = (const float4*)&xs[r2][kg * 16];
            unsigned long long acc = 0ull;
#pragma unroll
            for (int j = 0; j < 4; j++) {
                float4 xv = xp[j];
                fma2(acc, pk2(xv.x, xv.x), wp[4 * j + 0]);
                fma2(acc, pk2(xv.y, xv.y), wp[4 * j + 1]);
                fma2(acc, pk2(xv.z, xv.z), wp[4 * j + 2]);
                fma2(acc, pk2(xv.w, xv.w), wp[4 * j + 3]);
            }
            float sc, sd;
            upk2(acc, sc, sd);
            sc += __shfl_xor_sync(0xffffffffu, sc, 1);
            sc += __shfl_xor_sync(0xffffffffu, sc, 2);
            sd += __shfl_xor_sync(0xffffffffu, sd, 1);
            sd += __shfl_xor_sync(0xffffffffu, sd, 2);
            float sc2 = __shfl_xor_sync(0xffffffffu, sc, 4);
            float sd2 = __shfl_xor_sync(0xffffffffu, sd, 4);

            if (kg == 0 && (o & 1) == 0) {
                __half* row = g_xi + (size_t)(m0 + r2) * (2 * C);
                *(__half2*)(row + o)     = __floats2half2_rn(sc, sc2);
                *(__half2*)(row + C + o) = __floats2half2_rn(sd, sd2);
            }
        }
    }
}

// ---------------------------------------------------------------------------
// Gather v2: bucket metadata staged ONCE per warp into warp-private shared
// (coalesced), killing the 8x-redundant global meta wavefronts and the meta
// L2 scoreboard chain. One warp per (node,batch), batch-major; four 8-lane
// groups x 4 edges per trip; rows via LDG.128; fp16 core, f32x2 flush.
// ---------------------------------------------------------------------------
__global__ void __launch_bounds__(128, 6)
gather_kernel(const float* __restrict__ bias, float* __restrict__ out) {
    __shared__ __align__(16) float4 smeta[4][CAP];   // 12 KB / block

    const int w = (int)((blockIdx.x * blockDim.x + threadIdx.x) >> 5);
    if (w >= BATCH * N_NODES) return;
    const int b    = (w < N_NODES) ? 0 : 1;
    const int n    = (w < N_NODES) ? w : (w - N_NODES);
    const int lane = threadIdx.x & 31;
    const int g    = lane >> 3;        // edge group 0..3
    const int l8   = lane & 7;         // 8 channels: l8*8 .. +8

    const int cnt = g_cnt[n];
    const int beg = n * CAP;
    float4* sm = smeta[threadIdx.x >> 5];

    // stage this node's whole bucket (contiguous, coalesced)
    for (int j = lane; j < cnt; j += 32)
        sm[j] = __ldg(&g_em[beg + j]);
    __syncwarp();

    const __half*  __restrict__ xib = g_xi + (size_t)b * N_NODES * (2 * C);

    unsigned long long a0 = 0ull, a1 = 0ull, a2 = 0ull, a3 = 0ull;

    if (g == 0) {   // self-loop + bias init
        const float4 ni = g_ni[n];
        const float nrm = ni.z * ni.z;
        const float4 b0 = *(const float4*)(bias + l8 * 8);
        const float4 b1 = *(const float4*)(bias + l8 * 8 + 4);
        const uint4  xh = *(const uint4*)(xib + (size_t)n * (2 * C) + l8 * 8);
        const float2 x0 = __half22float2(*(const __half2*)&xh.x);
        const float2 x1 = __half22float2(*(const __half2*)&xh.y);
        const float2 x2 = __half22float2(*(const __half2*)&xh.z);
        const float2 x3 = __half22float2(*(const __half2*)&xh.w);
        a0 = pk2(fmaf(nrm, x0.x, b0.x), fmaf(nrm, x0.y, b0.y));
        a1 = pk2(fmaf(nrm, x1.x, b0.z), fmaf(nrm, x1.y, b0.w));
        a2 = pk2(fmaf(nrm, x2.x, b1.x), fmaf(nrm, x2.y, b1.y));
        a3 = pk2(fmaf(nrm, x3.x, b1.z), fmaf(nrm, x3.y, b1.w));
    }

    int e = g;                         // this group's slots: e, e+4, e+8, e+12
    if (e < cnt) {
        // first 4 metas from shared (clamped; slot 0 always valid here)
        float3 m[4];
#pragma unroll
        for (int k = 0; k < 4; k++) {
            const int  j = e + 4 * k;
            const bool v = (j < cnt);
            const float4 t = sm[v ? j : 0];
            const float cC = v ? (b ? t.w : t.z) : 0.0f;
            const float nm = v ? t.y : 0.0f;
            m[k] = make_float3(t.x, cC, nm - cC);
        }

        for (;;) {
            // 1) issue all 8 row loads (max lines in flight)
            uint4 A[4], D[4];
#pragma unroll
            for (int k = 0; k < 4; k++) {
                const __half* row = xib +
                    (size_t)__float_as_int(m[k].x) * (2 * C) + l8 * 8;
                A[k] = __ldg((const uint4*)(row));
                D[k] = __ldg((const uint4*)(row + C));
            }

            // 2) prefetch next 4 metas from shared (cheap LDS)
            e += 16;
            const bool more = (e < cnt);
            float3 mn[4];
#pragma unroll
            for (int k = 0; k < 4; k++) {
                const int  j = e + 4 * k;
                const bool v = (j < cnt);
                const float4 t = sm[v ? j : 0];
                const float cC = v ? (b ? t.w : t.z) : 0.0f;
                const float nm = v ? t.y : 0.0f;
                mn[k] = make_float3(t.x, cC, nm - cC);
            }

            // 3) consume: fp16 core, flush every 2 edges
#pragma unroll
            for (int p = 0; p < 2; p++) {
                const int k0 = 2 * p, k1 = 2 * p + 1;
                const __half2 cc0 = __float2half2_rn(m[k0].y);
                const __half2 cd0 = __float2half2_rn(m[k0].z);
                const __half2 cc1 = __float2half2_rn(m[k1].y);
                const __half2 cd1 = __float2half2_rn(m[k1].z);
                const __half2* A0 = (const __half2*)&A[k0];
                const __half2* D0 = (const __half2*)&D[k0];
                const __half2* A1 = (const __half2*)&A[k1];
                const __half2* D1 = (const __half2*)&D[k1];

                __half2 h0 = __hmul2(A0[0], cc0);
                __half2 h1 = __hmul2(A0[1], cc0);
                __half2 h2 = __hmul2(A0[2], cc0);
                __half2 h3 = __hmul2(A0[3], cc0);
                h0 = __hfma2(D0[0], cd0, h0);
                h1 = __hfma2(D0[1], cd0, h1);
                h2 = __hfma2(D0[2], cd0, h2);
                h3 = __hfma2(D0[3], cd0, h3);
                h0 = __hfma2(A1[0], cc1, h0);
                h1 = __hfma2(A1[1], cc1, h1);
                h2 = __hfma2(A1[2], cc1, h2);
                h3 = __hfma2(A1[3], cc1, h3);
                h0 = __hfma2(D1[0], cd1, h0);
                h1 = __hfma2(D1[1], cd1, h1);
                h2 = __hfma2(D1[2], cd1, h2);
                h3 = __hfma2(D1[3], cd1, h3);

                float2 f;
                f = __half22float2(h0); add2(a0, pk2(f.x, f.y));
                f = __half22float2(h1); add2(a1, pk2(f.x, f.y));
                f = __half22float2(h2); add2(a2, pk2(f.x, f.y));
                f = __half22float2(h3); add2(a3, pk2(f.x, f.y));
            }

            if (!more) break;
#pragma unroll
            for (int k = 0; k < 4; k++) m[k] = mn[k];
        }
    }

    // reduce the 4 groups
    float f0, f1, f2, f3, f4, f5, f6, f7;
    upk2(a0, f0, f1); upk2(a1, f2, f3); upk2(a2, f4, f5); upk2(a3, f6, f7);
#pragma unroll
    for (int d = 8; d <= 16; d <<= 1) {
        f0 += __shfl_xor_sync(0xffffffffu, f0, d);
        f1 += __shfl_xor_sync(0xffffffffu, f1, d);
        f2 += __shfl_xor_sync(0xffffffffu, f2, d);
        f3 += __shfl_xor_sync(0xffffffffu, f3, d);
        f4 += __shfl_xor_sync(0xffffffffu, f4, d);
        f5 += __shfl_xor_sync(0xffffffffu, f5, d);
        f6 += __shfl_xor_sync(0xffffffffu, f6, d);
        f7 += __shfl_xor_sync(0xffffffffu, f7, d);
    }

    if (g == 0) {
        float* orow = out + ((size_t)b * N_NODES + n) * C + l8 * 8;
        *(float4*)(orow)     = make_float4(f0, f1, f2, f3);
        *(float4*)(orow + 4) = make_float4(f4, f5, f6, f7);
    }
}

// ---------------------------------------------------------------------------
extern "C" void kernel_launch(void* const* d_in, const int* in_sizes, int n_in,
                              void* d_out, int out_size) {
    const float* x    = (const float*)d_in[0];
    const int*   ei   = (const int*)d_in[1];
    const float* fdo  = (const float*)d_in[2];
    const float* flux = (const float*)d_in[3];
    const float* Wc   = (const float*)d_in[4];
    const float* Wd   = (const float*)d_in[5];
    const float* bias = (const float*)d_in[6];
    float* out = (float*)d_out;

    static cudaStream_t s2 = nullptr;
    static cudaEvent_t evFork = nullptr, evJoin = nullptr;
    if (!s2) {
        cudaStreamCreateWithFlags(&s2, cudaStreamNonBlocking);
        cudaEventCreateWithFlags(&evFork, cudaEventDisableTiming);
        cudaEventCreateWithFlags(&evJoin, cudaEventDisableTiming);
    }

    cudaEventRecord(evFork, 0);
    cudaStreamWaitEvent(s2, evFork, 0);
    gemm_kernel<<<2960, 256, 0, s2>>>(x, Wc, Wd);
    cudaEventRecord(evJoin, s2);

    detect_zero_kernel<<<NBLK, 256>>>((const unsigned int*)ei);
    hist_kernel<<<(N_EDGES / 4 + 255) / 256, 256>>>(ei);
    ni_kernel<<<NBLK, 256>>>(flux);
    fill_kernel<<<(N_EDGES + 255) / 256, 256>>>(ei, fdo);

    cudaStreamWaitEvent(0, evJoin, 0);
    gather_kernel<<<(BATCH * N_NODES * 32 + 127) / 128, 128>>>(bias, out);
}